// round 4
// baseline (speedup 1.0000x reference)
#include <cuda_runtime.h>
#include <cstdint>

// Problem constants
#define BATCH   16
#define CDIM    64          // EMBEDDING_DIM
#define HW      4096        // 64*64
#define KTOT    1024        // NUM_EMBEDDINGS
#define NTOT    (BATCH*HW)  // 65536 flat vectors
#define TM      128         // positions per block tile
#define TK      128         // codes per chunk
#define NCHUNK  (KTOT/TK)   // 8
#define NBLOCKS (NTOT/TM)   // 512
#define ELEMS   ((size_t)BATCH*CDIM*HW)   // 4194304

// Output layout: [loss(1)][quantized NCHW(4194304)][indices(65536)]
#define OUT_Q    1
#define OUT_IDX  (1 + (size_t)ELEMS)

typedef unsigned long long u64;

// Scratch (device globals — no allocation allowed)
__device__ float g_scratch[NBLOCKS];    // per-block loss partials
__device__ int   g_count = 0;           // completion counter (self-resetting)

// ---------------- packed f32x2 helpers ----------------
__device__ __forceinline__ u64 fma2(u64 a, u64 b, u64 c) {
    u64 d;
    asm("fma.rn.f32x2 %0, %1, %2, %3;" : "=l"(d) : "l"(a), "l"(b), "l"(c));
    return d;
}
__device__ __forceinline__ void unpack2(u64 v, float& lo, float& hi) {
    asm("mov.b64 {%0, %1}, %2;" : "=f"(lo), "=f"(hi) : "l"(v));
}

// ---------------- fused kernel ----------------
// One block = 128 positions. 256 threads = 16(ty: j) x 16(tx: k); 8x8 tile/thread.
// Thread's k set: {4*tx + g*64 + p : p=0..3, g=0..1}  (2x LDS.128, conflict-free)
// smem: xs2[64][128] float2 dup | es[64][128] | en[128] | xn[128] | idx[128]
#define SMEM_BYTES (CDIM*TM*8 + CDIM*TK*4 + TM*4 + TM*4 + TM*4)

__global__ __launch_bounds__(256, 2)
void vq_all(const float* __restrict__ xin_all, const float* __restrict__ emb,
            float* __restrict__ out) {
    extern __shared__ float sm[];
    float* xs2  = sm;                         // [64][128] float2 dup  (64KB)
    float* es   = sm + CDIM * TM * 2;         // [64][128]             (32KB)
    float* en_s = es + CDIM * TK;             // [128]
    float* xn_s = en_s + TM;                  // [128]
    int*   idx_s = (int*)(xn_s + TM);         // [128]
    // overlays (phase 2, xs2/es dead)
    float* rs = xs2;                          // [128][16] scores
    int*   ri = (int*)(xs2 + TM * 16);        // [128][16] indices
    float* qs = es;                           // [64][128] quantized tile

    const int tid = threadIdx.x;
    const int b   = blockIdx.x >> 5;
    const int hw0 = (blockIdx.x & 31) * TM;
    const float* xin = xin_all + (size_t)b * CDIM * HW + hw0;

    // Load X tile, duplicated pairs (x,x) -> xs2
    #pragma unroll
    for (int p = 0; p < 8; p++) {
        int c = (tid >> 5) + p * 8;
        int j = (tid & 31) * 4;
        float4 v = *(const float4*)(xin + (size_t)c * HW + j);
        float4* d = (float4*)(xs2 + 2 * (c * TM + j));
        d[0] = make_float4(v.x, v.x, v.y, v.y);
        d[1] = make_float4(v.z, v.z, v.w, v.w);
    }
    __syncthreads();

    // ||x_j||^2
    if (tid < TM) {
        float s = 0.f;
        #pragma unroll 8
        for (int c = 0; c < CDIM; c++) { float v = xs2[2 * (c * TM + tid)]; s += v * v; }
        xn_s[tid] = s;
    }

    const int ty = tid >> 4;   // j group
    const int tx = tid & 15;   // k group
    float best[8];
    int   bidx[8];
    #pragma unroll
    for (int jj = 0; jj < 8; jj++) { best[jj] = 3.4e38f; bidx[jj] = 0x7fffffff; }

    // loader mapping for e-chunk transpose: thread t -> code row klocal, 32 c's
    const int kl = tid >> 1;              // 0..127
    const int ch = (tid & 1) * 32;        // c half

    for (int chunk = 0; chunk < NCHUNK; chunk++) {
        const int kbase = chunk * TK;

        // Load e-chunk rows from emb (row-major, L2-hot), transpose into es,
        // fuse ||e||^2 partial.
        float4 ev[8];
        const float4* erow = (const float4*)(emb + (size_t)(kbase + kl) * CDIM + ch);
        #pragma unroll
        for (int q = 0; q < 8; q++) ev[q] = erow[q];

        __syncthreads();   // previous chunk compute done before es overwrite
        float p2 = 0.f;
        #pragma unroll
        for (int q = 0; q < 8; q++) {
            float4 v = ev[q];
            int c = ch + q * 4;
            es[(c + 0) * TK + kl] = v.x;
            es[(c + 1) * TK + kl] = v.y;
            es[(c + 2) * TK + kl] = v.z;
            es[(c + 3) * TK + kl] = v.w;
            p2 += v.x * v.x + v.y * v.y + v.z * v.z + v.w * v.w;
        }
        p2 += __shfl_xor_sync(0xffffffffu, p2, 1);
        if ((tid & 1) == 0) en_s[kl] = p2;
        __syncthreads();

        u64 acc[8][4];
        #pragma unroll
        for (int jj = 0; jj < 8; jj++)
            #pragma unroll
            for (int m = 0; m < 4; m++) acc[jj][m] = 0ull;

        #pragma unroll 4
        for (int c = 0; c < CDIM; c++) {
            const ulonglong2* xp = (const ulonglong2*)(xs2 + 2 * (c * TM + ty * 8));
            ulonglong2 xv0 = xp[0], xv1 = xp[1], xv2 = xp[2], xv3 = xp[3];
            const ulonglong2* eg0 = (const ulonglong2*)(es + c * TK + 4 * tx);
            const ulonglong2* eg1 = (const ulonglong2*)(es + c * TK + 64 + 4 * tx);
            ulonglong2 e0 = eg0[0];    // k: 4tx .. 4tx+3
            ulonglong2 e1 = eg1[0];    // k: 64+4tx .. 64+4tx+3
            u64 xj[8] = {xv0.x, xv0.y, xv1.x, xv1.y, xv2.x, xv2.y, xv3.x, xv3.y};
            #pragma unroll
            for (int jj = 0; jj < 8; jj++) {
                acc[jj][0] = fma2(xj[jj], e0.x, acc[jj][0]);
                acc[jj][1] = fma2(xj[jj], e0.y, acc[jj][1]);
                acc[jj][2] = fma2(xj[jj], e1.x, acc[jj][2]);
                acc[jj][3] = fma2(xj[jj], e1.y, acc[jj][3]);
            }
        }

        // scores: ||e||^2 - 2 x.e ; process ascending k => strict < keeps first
        #pragma unroll
        for (int g = 0; g < 2; g++) {
            const int klo = 4 * tx + 64 * g;
            const int k0  = kbase + klo;
            float4 en4 = *(const float4*)(en_s + klo);
            float en_[4] = {en4.x, en4.y, en4.z, en4.w};
            #pragma unroll
            for (int jj = 0; jj < 8; jj++) {
                #pragma unroll
                for (int m = 0; m < 2; m++) {
                    float lo, hi;
                    unpack2(acc[jj][2 * g + m], lo, hi);
                    float s0 = en_[2 * m]     - (lo + lo);
                    float s1 = en_[2 * m + 1] - (hi + hi);
                    if (s0 < best[jj]) { best[jj] = s0; bidx[jj] = k0 + 2 * m; }
                    if (s1 < best[jj]) { best[jj] = s1; bidx[jj] = k0 + 2 * m + 1; }
                }
            }
        }
    }

    __syncthreads();   // done with xs2/es reads; overlays safe
    #pragma unroll
    for (int jj = 0; jj < 8; jj++) {
        int j = ty * 8 + jj;
        rs[j * 16 + tx] = best[jj];
        ri[j * 16 + tx] = bidx[jj];
    }
    __syncthreads();

    if (tid < TM) {
        float bs = rs[tid * 16];
        int   bk = ri[tid * 16];
        #pragma unroll
        for (int t = 1; t < 16; t++) {
            float s = rs[tid * 16 + t];
            int   k = ri[tid * 16 + t];
            if (s < bs || (s == bs && k < bk)) { bs = s; bk = k; }
        }
        idx_s[tid] = bk;
        out[OUT_IDX + (size_t)b * HW + hw0 + tid] = (float)bk;
        xn_s[tid] = bs + xn_s[tid];   // dist = score + ||x||^2
    }
    __syncthreads();

    // Gather emb rows (contiguous 256B each) into qs, transposed to [c][j]
    {
        const int jq = tid >> 1;
        const int c0 = (tid & 1) * 32;
        const int kq = idx_s[jq];
        const float4* erow = (const float4*)(emb + (size_t)kq * CDIM + c0);
        #pragma unroll
        for (int q = 0; q < 8; q++) {
            float4 v = erow[q];
            int c = c0 + q * 4;
            qs[(c + 0) * TM + jq] = v.x;
            qs[(c + 1) * TM + jq] = v.y;
            qs[(c + 2) * TM + jq] = v.z;
            qs[(c + 3) * TM + jq] = v.w;
        }
    }
    if (tid < 64) xn_s[tid] += xn_s[tid + 64];
    __syncthreads();

    if (tid < 32) {
        float v = xn_s[tid] + xn_s[tid + 32];
        v += __shfl_xor_sync(0xffffffffu, v, 16);
        v += __shfl_xor_sync(0xffffffffu, v, 8);
        v += __shfl_xor_sync(0xffffffffu, v, 4);
        v += __shfl_xor_sync(0xffffffffu, v, 2);
        v += __shfl_xor_sync(0xffffffffu, v, 1);
        if (tid == 0) g_scratch[blockIdx.x] = v;
    }

    // Coalesced quantized write — SCALAR stores (out+1 breaks 16B alignment).
    {
        float* qbase = out + OUT_Q + (size_t)b * CDIM * HW + hw0;
        const int lane = tid & 31;
        #pragma unroll
        for (int p = 0; p < 8; p++) {
            int c = (tid >> 5) + p * 8;
            #pragma unroll
            for (int q = 0; q < 4; q++) {
                int j = lane + q * 32;
                qbase[(size_t)c * HW + j] = qs[c * TM + j];
            }
        }
    }

    // ---- fused final loss: last block reduces g_scratch ----
    __shared__ int s_last;
    __threadfence();
    if (tid == 0) {
        int old = atomicAdd(&g_count, 1);
        s_last = (old == NBLOCKS - 1) ? 1 : 0;
    }
    __syncthreads();
    if (s_last) {
        float v = g_scratch[tid] + g_scratch[tid + 256];
        v += __shfl_xor_sync(0xffffffffu, v, 16);
        v += __shfl_xor_sync(0xffffffffu, v, 8);
        v += __shfl_xor_sync(0xffffffffu, v, 4);
        v += __shfl_xor_sync(0xffffffffu, v, 2);
        v += __shfl_xor_sync(0xffffffffu, v, 1);
        if ((tid & 31) == 0) xn_s[tid >> 5] = v;   // reuse smem (8 warps)
        __syncthreads();
        if (tid == 0) {
            float s = 0.f;
            #pragma unroll
            for (int w = 0; w < 8; w++) s += xn_s[w];
            out[0] = 0.25f * s / (float)ELEMS;
            g_count = 0;   // reset for next graph replay
        }
    }
}

extern "C" void kernel_launch(void* const* d_in, const int* in_sizes, int n_in,
                              void* d_out, int out_size) {
    const float* x   = (const float*)d_in[0];   // [16,64,64,64] NCHW
    const float* emb = (const float*)d_in[1];   // [1024,64]
    float* out = (float*)d_out;

    cudaFuncSetAttribute(vq_all, cudaFuncAttributeMaxDynamicSharedMemorySize,
                         SMEM_BYTES);
    vq_all<<<NBLOCKS, 256, SMEM_BYTES>>>(x, emb, out);
}

// round 8
// speedup vs baseline: 1.0243x; 1.0243x over previous
#include <cuda_runtime.h>
#include <cstdint>

// Problem constants
#define BATCH   16
#define CDIM    64
#define HW      4096
#define KTOT    1024
#define NTOT    (BATCH*HW)
#define TM      128         // positions per block
#define TK      64          // codes per chunk
#define NCHUNK  (KTOT/TK)   // 16
#define NBLOCKS (NTOT/TM)   // 512
#define ELEMS   ((size_t)BATCH*CDIM*HW)   // 4194304

// Output layout: [loss(1)][quantized NCHW(4194304)][indices(65536)]
#define OUT_Q    1
#define OUT_IDX  (1 + (size_t)ELEMS)

typedef unsigned long long u64;

// Scratch (device globals)
__device__ float g_eT2[CDIM * KTOT * 2];  // e transposed+duplicated: [c][2k],[2k+1]
__device__ float g_enorm[KTOT];           // ||e_k||^2
__device__ float g_scratch[NBLOCKS];      // per-block loss partials
__device__ int   g_count = 0;             // completion counter (self-resetting)

// ---------------- packed f32x2 helpers ----------------
__device__ __forceinline__ u64 fma2(u64 a, u64 b, u64 c) {
    u64 d;
    asm("fma.rn.f32x2 %0, %1, %2, %3;" : "=l"(d) : "l"(a), "l"(b), "l"(c));
    return d;
}
__device__ __forceinline__ void unpack2(u64 v, float& lo, float& hi) {
    asm("mov.b64 {%0, %1}, %2;" : "=f"(lo), "=f"(hi) : "l"(v));
}

// ---------------- prep: transpose+duplicate embedding, code norms ----------------
__global__ void vq_prep(const float* __restrict__ emb) {
    int t = threadIdx.x;
    int k = blockIdx.x * 16 + (t >> 4);
    int c = (t & 15) * 4;
    float4 v = *(const float4*)(emb + (size_t)k * CDIM + c);
    float vv[4] = {v.x, v.y, v.z, v.w};
    #pragma unroll
    for (int i = 0; i < 4; i++) {
        float2 d2 = make_float2(vv[i], vv[i]);
        *(float2*)(g_eT2 + (size_t)(c + i) * (2 * KTOT) + 2 * k) = d2;
    }
    float p = v.x * v.x + v.y * v.y + v.z * v.z + v.w * v.w;
    p += __shfl_xor_sync(0xffffffffu, p, 1);
    p += __shfl_xor_sync(0xffffffffu, p, 2);
    p += __shfl_xor_sync(0xffffffffu, p, 4);
    p += __shfl_xor_sync(0xffffffffu, p, 8);
    if ((t & 15) == 0) g_enorm[k] = p;
}

// ---------------- main: distances + argmin + outputs + fused loss ----------------
// 256 threads = 16(ty: j-groups of 8) x 16(tx: k). Per thread: 8 j (4 lane-pairs) x 4 k.
// k set: {tx, 16+tx, 32+tx, 48+tx}. e duplicated in smem; x plain (j-pairs in lanes).
// smem: xs[64][128] (32KB) | es2[64][64*2] (32KB) | en[64] | xn[128] | idx[128]
#define SMEM_BYTES (CDIM*TM*4 + CDIM*TK*8 + TK*4 + TM*4 + TM*4)

__global__ __launch_bounds__(256, 3)
void vq_main(const float* __restrict__ xin_all, const float* __restrict__ emb,
             float* __restrict__ out) {
    extern __shared__ float sm[];
    float* xs   = sm;                         // [64][128]     32KB
    float* es2  = sm + CDIM * TM;             // [64][128] dup 32KB
    float* en_s = es2 + CDIM * TK * 2;        // [64]
    float* xn_s = en_s + TK;                  // [128]
    int*   idx_s = (int*)(xn_s + TM);         // [128]
    // overlays (phase 2)
    float* rs = xs;                           // [128][16] scores
    int*   ri = (int*)(xs + TM * 16);         // [128][16] indices
    float* qs = es2;                          // [64][128] quantized tile

    const int tid = threadIdx.x;
    const int b   = blockIdx.x >> 5;
    const int hw0 = (blockIdx.x & 31) * TM;
    const float* xin = xin_all + (size_t)b * CDIM * HW + hw0;

    // Load X tile (plain, coalesced)
    #pragma unroll
    for (int p = 0; p < 8; p++) {
        int c = (tid >> 5) + p * 8;
        int j = (tid & 31) * 4;
        *(float4*)(xs + c * TM + j) = *(const float4*)(xin + (size_t)c * HW + j);
    }
    __syncthreads();

    // ||x_j||^2
    if (tid < TM) {
        float s = 0.f;
        #pragma unroll 8
        for (int c = 0; c < CDIM; c++) { float v = xs[c * TM + tid]; s += v * v; }
        xn_s[tid] = s;
    }

    const int ty = tid >> 4;   // j group (8 j's)
    const int tx = tid & 15;   // k lane
    float best[8];
    int   bidx[8];
    #pragma unroll
    for (int jj = 0; jj < 8; jj++) { best[jj] = 3.4e38f; bidx[jj] = 0x7fffffff; }

    // chunk loader mapping: c row = tid>>2, quarter = tid&3 (32 floats each)
    const int lc = tid >> 2;
    const int lq = (tid & 3) * 32;

    for (int chunk = 0; chunk < NCHUNK; chunk++) {
        const int kbase = chunk * TK;

        __syncthreads();   // previous chunk compute done
        {
            const float* src = g_eT2 + (size_t)lc * (2 * KTOT) + 2 * kbase + lq;
            float* dst = es2 + lc * (2 * TK) + lq;
            #pragma unroll
            for (int q = 0; q < 8; q++)
                *(float4*)(dst + q * 4) = *(const float4*)(src + q * 4);
            if (tid < TK) en_s[tid] = g_enorm[kbase + tid];
        }
        __syncthreads();

        u64 acc[4][4];
        #pragma unroll
        for (int jp = 0; jp < 4; jp++)
            #pragma unroll
            for (int m = 0; m < 4; m++) acc[jp][m] = 0ull;

        #pragma unroll 4
        for (int c = 0; c < CDIM; c++) {
            const ulonglong2* xp = (const ulonglong2*)(xs + c * TM + ty * 8);
            ulonglong2 xa = xp[0], xb = xp[1];
            u64 xj[4] = {xa.x, xa.y, xb.x, xb.y};   // j-pairs
            const float* er = es2 + c * (2 * TK) + 2 * tx;
            u64 e0 = *(const u64*)(er);
            u64 e1 = *(const u64*)(er + 32);
            u64 e2 = *(const u64*)(er + 64);
            u64 e3 = *(const u64*)(er + 96);
            #pragma unroll
            for (int jp = 0; jp < 4; jp++) {
                acc[jp][0] = fma2(xj[jp], e0, acc[jp][0]);
                acc[jp][1] = fma2(xj[jp], e1, acc[jp][1]);
                acc[jp][2] = fma2(xj[jp], e2, acc[jp][2]);
                acc[jp][3] = fma2(xj[jp], e3, acc[jp][3]);
            }
        }

        // scores: ||e||^2 - 2 x.e ; m ascending => per-thread k ascending
        #pragma unroll
        for (int m = 0; m < 4; m++) {
            const int k0 = kbase + tx + 16 * m;
            const float en = en_s[tx + 16 * m];
            #pragma unroll
            for (int jp = 0; jp < 4; jp++) {
                float lo, hi;
                unpack2(acc[jp][m], lo, hi);
                float s0 = en - (lo + lo);   // j = ty*8 + 2*jp
                float s1 = en - (hi + hi);   // j = ty*8 + 2*jp + 1
                if (s0 < best[2 * jp])     { best[2 * jp] = s0;     bidx[2 * jp] = k0; }
                if (s1 < best[2 * jp + 1]) { best[2 * jp + 1] = s1; bidx[2 * jp + 1] = k0; }
            }
        }
    }

    __syncthreads();   // done with xs/es2; overlays safe
    #pragma unroll
    for (int jj = 0; jj < 8; jj++) {
        int j = ty * 8 + jj;
        rs[j * 16 + tx] = best[jj];
        ri[j * 16 + tx] = bidx[jj];
    }
    __syncthreads();

    if (tid < TM) {
        float bs = rs[tid * 16];
        int   bk = ri[tid * 16];
        #pragma unroll
        for (int t = 1; t < 16; t++) {
            float s = rs[tid * 16 + t];
            int   k = ri[tid * 16 + t];
            if (s < bs || (s == bs && k < bk)) { bs = s; bk = k; }
        }
        idx_s[tid] = bk;
        out[OUT_IDX + (size_t)b * HW + hw0 + tid] = (float)bk;
        xn_s[tid] = bs + xn_s[tid];   // dist = score + ||x||^2
    }
    __syncthreads();

    // Gather emb rows (contiguous 256B) into qs, transposed to [c][j]
    {
        const int jq = tid >> 1;
        const int c0 = (tid & 1) * 32;
        const int kq = idx_s[jq];
        const float4* erow = (const float4*)(emb + (size_t)kq * CDIM + c0);
        #pragma unroll
        for (int q = 0; q < 8; q++) {
            float4 v = erow[q];
            int c = c0 + q * 4;
            qs[(c + 0) * TM + jq] = v.x;
            qs[(c + 1) * TM + jq] = v.y;
            qs[(c + 2) * TM + jq] = v.z;
            qs[(c + 3) * TM + jq] = v.w;
        }
    }
    if (tid < 64) xn_s[tid] += xn_s[tid + 64];
    __syncthreads();

    if (tid < 32) {
        float v = xn_s[tid] + xn_s[tid + 32];
        v += __shfl_xor_sync(0xffffffffu, v, 16);
        v += __shfl_xor_sync(0xffffffffu, v, 8);
        v += __shfl_xor_sync(0xffffffffu, v, 4);
        v += __shfl_xor_sync(0xffffffffu, v, 2);
        v += __shfl_xor_sync(0xffffffffu, v, 1);
        if (tid == 0) g_scratch[blockIdx.x] = v;
    }

    // Quantized write — SCALAR stores (out+1 breaks 16B alignment)
    {
        float* qbase = out + OUT_Q + (size_t)b * CDIM * HW + hw0;
        const int lane = tid & 31;
        #pragma unroll
        for (int p = 0; p < 8; p++) {
            int c = (tid >> 5) + p * 8;
            #pragma unroll
            for (int q = 0; q < 4; q++) {
                int j = lane + q * 32;
                qbase[(size_t)c * HW + j] = qs[c * TM + j];
            }
        }
    }

    // ---- fused final loss: last block reduces g_scratch ----
    __shared__ int s_last;
    __threadfence();
    if (tid == 0) {
        int old = atomicAdd(&g_count, 1);
        s_last = (old == NBLOCKS - 1) ? 1 : 0;
    }
    __syncthreads();
    if (s_last) {
        float v = g_scratch[tid] + g_scratch[tid + 256];
        v += __shfl_xor_sync(0xffffffffu, v, 16);
        v += __shfl_xor_sync(0xffffffffu, v, 8);
        v += __shfl_xor_sync(0xffffffffu, v, 4);
        v += __shfl_xor_sync(0xffffffffu, v, 2);
        v += __shfl_xor_sync(0xffffffffu, v, 1);
        if ((tid & 31) == 0) xn_s[tid >> 5] = v;
        __syncthreads();
        if (tid == 0) {
            float s = 0.f;
            #pragma unroll
            for (int w = 0; w < 8; w++) s += xn_s[w];
            out[0] = 0.25f * s / (float)ELEMS;
            g_count = 0;   // reset for next graph replay
        }
    }
}

extern "C" void kernel_launch(void* const* d_in, const int* in_sizes, int n_in,
                              void* d_out, int out_size) {
    const float* x   = (const float*)d_in[0];   // [16,64,64,64] NCHW
    const float* emb = (const float*)d_in[1];   // [1024,64]
    float* out = (float*)d_out;

    cudaFuncSetAttribute(vq_main, cudaFuncAttributeMaxDynamicSharedMemorySize,
                         SMEM_BYTES);
    vq_prep<<<KTOT / 16, 256>>>(emb);
    vq_main<<<NBLOCKS, 256, SMEM_BYTES>>>(x, emb, out);
}

// round 9
// speedup vs baseline: 1.0758x; 1.0503x over previous
#include <cuda_runtime.h>
#include <cstdint>

// Problem constants
#define BATCH   16
#define CDIM    64
#define HW      4096
#define KTOT    1024
#define NTOT    (BATCH*HW)
#define TM      128         // positions per block
#define TK      128         // codes per chunk
#define NCHUNK  (KTOT/TK)   // 8
#define NBLOCKS (NTOT/TM)   // 512
#define ELEMS   ((size_t)BATCH*CDIM*HW)   // 4194304

// Output layout: [loss(1)][quantized NCHW(4194304)][indices(65536)]
#define OUT_Q    1
#define OUT_IDX  (1 + (size_t)ELEMS)

typedef unsigned long long u64;

// Scratch (device globals)
__device__ float g_eT2[CDIM * KTOT * 2];  // e transposed+duplicated: [c][2k],[2k+1]
__device__ float g_enorm[KTOT];           // ||e_k||^2
__device__ float g_scratch[NBLOCKS];      // per-block loss partials
__device__ int   g_count = 0;             // completion counter (self-resetting)

// ---------------- packed f32x2 helpers ----------------
__device__ __forceinline__ u64 fma2(u64 a, u64 b, u64 c) {
    u64 d;
    asm("fma.rn.f32x2 %0, %1, %2, %3;" : "=l"(d) : "l"(a), "l"(b), "l"(c));
    return d;
}
__device__ __forceinline__ void unpack2(u64 v, float& lo, float& hi) {
    asm("mov.b64 {%0, %1}, %2;" : "=f"(lo), "=f"(hi) : "l"(v));
}

// ---------------- prep: transpose+duplicate embedding, code norms ----------------
__global__ void vq_prep(const float* __restrict__ emb) {
    int t = threadIdx.x;
    int k = blockIdx.x * 16 + (t >> 4);
    int c = (t & 15) * 4;
    float4 v = *(const float4*)(emb + (size_t)k * CDIM + c);
    float vv[4] = {v.x, v.y, v.z, v.w};
    #pragma unroll
    for (int i = 0; i < 4; i++) {
        float2 d2 = make_float2(vv[i], vv[i]);
        *(float2*)(g_eT2 + (size_t)(c + i) * (2 * KTOT) + 2 * k) = d2;
    }
    float p = v.x * v.x + v.y * v.y + v.z * v.z + v.w * v.w;
    p += __shfl_xor_sync(0xffffffffu, p, 1);
    p += __shfl_xor_sync(0xffffffffu, p, 2);
    p += __shfl_xor_sync(0xffffffffu, p, 4);
    p += __shfl_xor_sync(0xffffffffu, p, 8);
    if ((t & 15) == 0) g_enorm[k] = p;
}

// ---------------- main: distances + argmin + outputs + fused loss ----------------
// 256 threads = 16(ty) x 16(tx). Per thread: 8 j (4 f32x2 lane-pairs) x 8 k.
// k set: {tx + 16m, m=0..7}. e duplicated (e,e) in smem; x natural j-pairs.
// smem: xs[64][128] 32KB | es2[64][128*2] 64KB | en[128] | xn[128] | idx[128]
#define SMEM_BYTES (CDIM*TM*4 + CDIM*TK*8 + TK*4 + TM*4 + TM*4)

__global__ __launch_bounds__(256, 2)
void vq_main(const float* __restrict__ xin_all, const float* __restrict__ emb,
             float* __restrict__ out) {
    extern __shared__ float sm[];
    float* xs   = sm;                         // [64][128]      32KB
    float* es2  = sm + CDIM * TM;             // [64][256] dup  64KB
    float* en_s = es2 + CDIM * TK * 2;        // [128]
    float* xn_s = en_s + TK;                  // [128]
    int*   idx_s = (int*)(xn_s + TM);         // [128]
    // overlays (phase 2)
    float* rs = xs;                           // [128][16] scores
    int*   ri = (int*)(xs + TM * 16);         // [128][16] indices
    float* qs = es2;                          // [64][128] quantized tile

    const int tid = threadIdx.x;
    const int b   = blockIdx.x >> 5;
    const int hw0 = (blockIdx.x & 31) * TM;
    const float* xin = xin_all + (size_t)b * CDIM * HW + hw0;

    // Load X tile (plain, coalesced)
    #pragma unroll
    for (int p = 0; p < 8; p++) {
        int c = (tid >> 5) + p * 8;
        int j = (tid & 31) * 4;
        *(float4*)(xs + c * TM + j) = *(const float4*)(xin + (size_t)c * HW + j);
    }
    __syncthreads();

    // ||x_j||^2
    if (tid < TM) {
        float s = 0.f;
        #pragma unroll 8
        for (int c = 0; c < CDIM; c++) { float v = xs[c * TM + tid]; s += v * v; }
        xn_s[tid] = s;
    }

    const int ty = tid >> 4;   // j group (8 j's = 4 pairs)
    const int tx = tid & 15;   // k lane
    float best[8];
    int   bidx[8];
    #pragma unroll
    for (int jj = 0; jj < 8; jj++) { best[jj] = 3.4e38f; bidx[jj] = 0x7fffffff; }

    // chunk loader mapping: c row = tid>>2, quarter = (tid&3)*64 floats
    const int lc = tid >> 2;
    const int lq = (tid & 3) * 64;

    for (int chunk = 0; chunk < NCHUNK; chunk++) {
        const int kbase = chunk * TK;

        __syncthreads();   // previous chunk compute done
        {
            const float* src = g_eT2 + (size_t)lc * (2 * KTOT) + 2 * kbase + lq;
            float* dst = es2 + lc * (2 * TK) + lq;
            #pragma unroll
            for (int q = 0; q < 16; q++)
                *(float4*)(dst + q * 4) = *(const float4*)(src + q * 4);
            if (tid < TK) en_s[tid] = g_enorm[kbase + tid];
        }
        __syncthreads();

        u64 acc[4][8];
        #pragma unroll
        for (int jp = 0; jp < 4; jp++)
            #pragma unroll
            for (int m = 0; m < 8; m++) acc[jp][m] = 0ull;

        #pragma unroll 2
        for (int c = 0; c < CDIM; c++) {
            const ulonglong2* xp = (const ulonglong2*)(xs + c * TM + ty * 8);
            ulonglong2 xa = xp[0], xb = xp[1];
            u64 xj[4] = {xa.x, xa.y, xb.x, xb.y};   // natural j-pairs
            const float* er = es2 + c * (2 * TK) + 2 * tx;
            #pragma unroll
            for (int m = 0; m < 8; m++) {
                u64 e = *(const u64*)(er + 32 * m);  // (e_k, e_k) dup
                acc[0][m] = fma2(xj[0], e, acc[0][m]);
                acc[1][m] = fma2(xj[1], e, acc[1][m]);
                acc[2][m] = fma2(xj[2], e, acc[2][m]);
                acc[3][m] = fma2(xj[3], e, acc[3][m]);
            }
        }

        // scores: ||e||^2 - 2 x.e ; m ascending => per-thread k ascending
        #pragma unroll
        for (int m = 0; m < 8; m++) {
            const int k0 = kbase + tx + 16 * m;
            const float en = en_s[tx + 16 * m];
            #pragma unroll
            for (int jp = 0; jp < 4; jp++) {
                float lo, hi;
                unpack2(acc[jp][m], lo, hi);
                float s0 = en - (lo + lo);   // j = ty*8 + 2*jp
                float s1 = en - (hi + hi);   // j = ty*8 + 2*jp + 1
                if (s0 < best[2 * jp])     { best[2 * jp] = s0;     bidx[2 * jp] = k0; }
                if (s1 < best[2 * jp + 1]) { best[2 * jp + 1] = s1; bidx[2 * jp + 1] = k0; }
            }
        }
    }

    __syncthreads();   // done with xs/es2; overlays safe
    #pragma unroll
    for (int jj = 0; jj < 8; jj++) {
        int j = ty * 8 + jj;
        rs[j * 16 + tx] = best[jj];
        ri[j * 16 + tx] = bidx[jj];
    }
    __syncthreads();

    if (tid < TM) {
        float bs = rs[tid * 16];
        int   bk = ri[tid * 16];
        #pragma unroll
        for (int t = 1; t < 16; t++) {
            float s = rs[tid * 16 + t];
            int   k = ri[tid * 16 + t];
            if (s < bs || (s == bs && k < bk)) { bs = s; bk = k; }
        }
        idx_s[tid] = bk;
        out[OUT_IDX + (size_t)b * HW + hw0 + tid] = (float)bk;
        xn_s[tid] = bs + xn_s[tid];   // dist = score + ||x||^2
    }
    __syncthreads();

    // Gather emb rows (contiguous 256B) into qs, transposed to [c][j]
    {
        const int jq = tid >> 1;
        const int c0 = (tid & 1) * 32;
        const int kq = idx_s[jq];
        const float4* erow = (const float4*)(emb + (size_t)kq * CDIM + c0);
        #pragma unroll
        for (int q = 0; q < 8; q++) {
            float4 v = erow[q];
            int c = c0 + q * 4;
            qs[(c + 0) * TM + jq] = v.x;
            qs[(c + 1) * TM + jq] = v.y;
            qs[(c + 2) * TM + jq] = v.z;
            qs[(c + 3) * TM + jq] = v.w;
        }
    }
    if (tid < 64) xn_s[tid] += xn_s[tid + 64];
    __syncthreads();

    if (tid < 32) {
        float v = xn_s[tid] + xn_s[tid + 32];
        v += __shfl_xor_sync(0xffffffffu, v, 16);
        v += __shfl_xor_sync(0xffffffffu, v, 8);
        v += __shfl_xor_sync(0xffffffffu, v, 4);
        v += __shfl_xor_sync(0xffffffffu, v, 2);
        v += __shfl_xor_sync(0xffffffffu, v, 1);
        if (tid == 0) g_scratch[blockIdx.x] = v;
    }

    // Quantized write — SCALAR stores (out+1 breaks 16B alignment)
    {
        float* qbase = out + OUT_Q + (size_t)b * CDIM * HW + hw0;
        const int lane = tid & 31;
        #pragma unroll
        for (int p = 0; p < 8; p++) {
            int c = (tid >> 5) + p * 8;
            #pragma unroll
            for (int q = 0; q < 4; q++) {
                int j = lane + q * 32;
                qbase[(size_t)c * HW + j] = qs[c * TM + j];
            }
        }
    }

    // ---- fused final loss: last block reduces g_scratch ----
    __shared__ int s_last;
    __threadfence();
    if (tid == 0) {
        int old = atomicAdd(&g_count, 1);
        s_last = (old == NBLOCKS - 1) ? 1 : 0;
    }
    __syncthreads();
    if (s_last) {
        float v = g_scratch[tid] + g_scratch[tid + 256];
        v += __shfl_xor_sync(0xffffffffu, v, 16);
        v += __shfl_xor_sync(0xffffffffu, v, 8);
        v += __shfl_xor_sync(0xffffffffu, v, 4);
        v += __shfl_xor_sync(0xffffffffu, v, 2);
        v += __shfl_xor_sync(0xffffffffu, v, 1);
        if ((tid & 31) == 0) xn_s[tid >> 5] = v;
        __syncthreads();
        if (tid == 0) {
            float s = 0.f;
            #pragma unroll
            for (int w = 0; w < 8; w++) s += xn_s[w];
            out[0] = 0.25f * s / (float)ELEMS;
            g_count = 0;   // reset for next graph replay
        }
    }
}

extern "C" void kernel_launch(void* const* d_in, const int* in_sizes, int n_in,
                              void* d_out, int out_size) {
    const float* x   = (const float*)d_in[0];   // [16,64,64,64] NCHW
    const float* emb = (const float*)d_in[1];   // [1024,64]
    float* out = (float*)d_out;

    cudaFuncSetAttribute(vq_main, cudaFuncAttributeMaxDynamicSharedMemorySize,
                         SMEM_BYTES);
    vq_prep<<<KTOT / 16, 256>>>(emb);
    vq_main<<<NBLOCKS, 256, SMEM_BYTES>>>(x, emb, out);
}

// round 11
// speedup vs baseline: 1.6698x; 1.5522x over previous
#include <cuda_runtime.h>
#include <cstdint>

// Problem constants
#define BATCH   16
#define CDIM    64
#define HW      4096
#define KTOT    1024
#define NTOT    (BATCH*HW)
#define TM      128         // positions per block
#define TK      128         // codes per chunk
#define NCHUNK  (KTOT/TK)   // 8
#define NBLOCKS (NTOT/TM)   // 512
#define ELEMS   ((size_t)BATCH*CDIM*HW)   // 4194304

// Output layout: [loss(1)][quantized NCHW(4194304)][indices(65536)]
#define OUT_Q    1
#define OUT_IDX  (1 + (size_t)ELEMS)

typedef unsigned long long u64;

// Scratch (device globals)
__device__ float g_eT[CDIM * KTOT];       // embedding transposed [c][k]
__device__ float g_enorm[KTOT];           // ||e_k||^2
__device__ float g_scratch[NBLOCKS];      // per-block loss partials
__device__ int   g_count = 0;             // completion counter (self-resetting)

// ---------------- packed f32x2 helpers ----------------
__device__ __forceinline__ u64 fma2(u64 a, u64 b, u64 c) {
    u64 d;
    asm("fma.rn.f32x2 %0, %1, %2, %3;" : "=l"(d) : "l"(a), "l"(b), "l"(c));
    return d;
}
__device__ __forceinline__ u64 pack2(float a) {      // (a,a) — ALU movs, no L1
    u64 r;
    asm("mov.b64 %0, {%1, %1};" : "=l"(r) : "f"(a));
    return r;
}
__device__ __forceinline__ void unpack2(u64 v, float& lo, float& hi) {
    asm("mov.b64 {%0, %1}, %2;" : "=f"(lo), "=f"(hi) : "l"(v));
}

// ---------------- prep: transpose embedding + code norms ----------------
__global__ void vq_prep(const float* __restrict__ emb) {
    int t = threadIdx.x;
    int k = blockIdx.x * 16 + (t >> 4);
    int c = (t & 15) * 4;
    float4 v = *(const float4*)(emb + (size_t)k * CDIM + c);
    g_eT[(size_t)(c + 0) * KTOT + k] = v.x;
    g_eT[(size_t)(c + 1) * KTOT + k] = v.y;
    g_eT[(size_t)(c + 2) * KTOT + k] = v.z;
    g_eT[(size_t)(c + 3) * KTOT + k] = v.w;
    float p = v.x * v.x + v.y * v.y + v.z * v.z + v.w * v.w;
    p += __shfl_xor_sync(0xffffffffu, p, 1);
    p += __shfl_xor_sync(0xffffffffu, p, 2);
    p += __shfl_xor_sync(0xffffffffu, p, 4);
    p += __shfl_xor_sync(0xffffffffu, p, 8);
    if ((t & 15) == 0) g_enorm[k] = p;
}

// ---------------- main: distances + argmin + outputs + fused loss ----------------
// 256 threads = 16(ty) x 16(tx). Per thread: 8 j (4 natural f32x2 pairs) x 8 k.
// k set: {4tx..4tx+3} U {64+4tx..64+4tx+3}  (2x LDS.128 e loads, plain e).
// e duplicated (e,e) in REGISTERS (ALU movs), x pairs come natural from LDS.128.
// smem: xs[64][128] 32KB | es[64][128] 32KB | en[128] | xn[128] | idx[128]
#define SMEM_BYTES (CDIM*TM*4 + CDIM*TK*4 + TK*4 + TM*4 + TM*4)

__global__ __launch_bounds__(256, 2)
void vq_main(const float* __restrict__ xin_all, const float* __restrict__ emb,
             float* __restrict__ out) {
    extern __shared__ float sm[];
    float* xs   = sm;                         // [64][128]  32KB
    float* es   = sm + CDIM * TM;             // [64][128]  32KB
    float* en_s = es + CDIM * TK;             // [128]
    float* xn_s = en_s + TK;                  // [128]
    int*   idx_s = (int*)(xn_s + TM);         // [128]
    // overlays (phase 2)
    float* rs = xs;                           // [128][16] scores
    int*   ri = (int*)(xs + TM * 16);         // [128][16] indices
    float* qs = es;                           // [64][128] quantized tile

    const int tid = threadIdx.x;
    const int b   = blockIdx.x >> 5;
    const int hw0 = (blockIdx.x & 31) * TM;
    const float* xin = xin_all + (size_t)b * CDIM * HW + hw0;

    // Load X tile (plain, coalesced)
    #pragma unroll
    for (int p = 0; p < 8; p++) {
        int c = (tid >> 5) + p * 8;
        int j = (tid & 31) * 4;
        *(float4*)(xs + c * TM + j) = *(const float4*)(xin + (size_t)c * HW + j);
    }
    __syncthreads();

    // ||x_j||^2
    if (tid < TM) {
        float s = 0.f;
        #pragma unroll 8
        for (int c = 0; c < CDIM; c++) { float v = xs[c * TM + tid]; s += v * v; }
        xn_s[tid] = s;
    }

    const int ty = tid >> 4;   // j group (8 j's = 4 pairs)
    const int tx = tid & 15;   // k group
    float best[8];
    int   bidx[8];
    #pragma unroll
    for (int jj = 0; jj < 8; jj++) { best[jj] = 3.4e38f; bidx[jj] = 0x7fffffff; }

    // chunk loader mapping: c row = tid>>2 (0..63), quarter = (tid&3)*32 floats
    const int lc = tid >> 2;
    const int lq = (tid & 3) * 32;

    for (int chunk = 0; chunk < NCHUNK; chunk++) {
        const int kbase = chunk * TK;

        __syncthreads();   // previous chunk compute done
        {
            const float* src = g_eT + (size_t)lc * KTOT + kbase + lq;
            float* dst = es + lc * TK + lq;
            #pragma unroll
            for (int q = 0; q < 8; q++)
                *(float4*)(dst + q * 4) = *(const float4*)(src + q * 4);
            if (tid < TK) en_s[tid] = g_enorm[kbase + tid];
        }
        __syncthreads();

        u64 acc[4][8];
        #pragma unroll
        for (int jp = 0; jp < 4; jp++)
            #pragma unroll
            for (int m = 0; m < 8; m++) acc[jp][m] = 0ull;

        #pragma unroll 4
        for (int c = 0; c < CDIM; c++) {
            const ulonglong2* xp = (const ulonglong2*)(xs + c * TM + ty * 8);
            ulonglong2 xa = xp[0], xb = xp[1];
            u64 xj[4] = {xa.x, xa.y, xb.x, xb.y};   // natural j-pairs
            float4 ea = *(const float4*)(es + c * TK + 4 * tx);
            float4 eb = *(const float4*)(es + c * TK + 64 + 4 * tx);
            u64 ep[8];
            ep[0] = pack2(ea.x); ep[1] = pack2(ea.y);
            ep[2] = pack2(ea.z); ep[3] = pack2(ea.w);
            ep[4] = pack2(eb.x); ep[5] = pack2(eb.y);
            ep[6] = pack2(eb.z); ep[7] = pack2(eb.w);
            #pragma unroll
            for (int m = 0; m < 8; m++) {
                acc[0][m] = fma2(xj[0], ep[m], acc[0][m]);
                acc[1][m] = fma2(xj[1], ep[m], acc[1][m]);
                acc[2][m] = fma2(xj[2], ep[m], acc[2][m]);
                acc[3][m] = fma2(xj[3], ep[m], acc[3][m]);
            }
        }

        // scores: ||e||^2 - 2 x.e ; m ascending => per-thread k ascending
        #pragma unroll
        for (int m = 0; m < 8; m++) {
            const int klocal = (m < 4) ? (4 * tx + m) : (64 + 4 * tx + m - 4);
            const int k0 = kbase + klocal;
            const float en = en_s[klocal];
            #pragma unroll
            for (int jp = 0; jp < 4; jp++) {
                float lo, hi;
                unpack2(acc[jp][m], lo, hi);
                float s0 = en - (lo + lo);   // j = ty*8 + 2*jp
                float s1 = en - (hi + hi);   // j = ty*8 + 2*jp + 1
                if (s0 < best[2 * jp])     { best[2 * jp] = s0;     bidx[2 * jp] = k0; }
                if (s1 < best[2 * jp + 1]) { best[2 * jp + 1] = s1; bidx[2 * jp + 1] = k0; }
            }
        }
    }

    __syncthreads();   // done with xs/es; overlays safe
    #pragma unroll
    for (int jj = 0; jj < 8; jj++) {
        int j = ty * 8 + jj;
        rs[j * 16 + tx] = best[jj];
        ri[j * 16 + tx] = bidx[jj];
    }
    __syncthreads();

    if (tid < TM) {
        float bs = rs[tid * 16];
        int   bk = ri[tid * 16];
        #pragma unroll
        for (int t = 1; t < 16; t++) {
            float s = rs[tid * 16 + t];
            int   k = ri[tid * 16 + t];
            if (s < bs || (s == bs && k < bk)) { bs = s; bk = k; }
        }
        idx_s[tid] = bk;
        out[OUT_IDX + (size_t)b * HW + hw0 + tid] = (float)bk;
        xn_s[tid] = bs + xn_s[tid];   // dist = score + ||x||^2
    }
    __syncthreads();

    // Gather emb rows (contiguous 256B) into qs, transposed to [c][j]
    {
        const int jq = tid >> 1;
        const int c0 = (tid & 1) * 32;
        const int kq = idx_s[jq];
        const float4* erow = (const float4*)(emb + (size_t)kq * CDIM + c0);
        #pragma unroll
        for (int q = 0; q < 8; q++) {
            float4 v = erow[q];
            int c = c0 + q * 4;
            qs[(c + 0) * TM + jq] = v.x;
            qs[(c + 1) * TM + jq] = v.y;
            qs[(c + 2) * TM + jq] = v.z;
            qs[(c + 3) * TM + jq] = v.w;
        }
    }
    if (tid < 64) xn_s[tid] += xn_s[tid + 64];
    __syncthreads();

    if (tid < 32) {
        float v = xn_s[tid] + xn_s[tid + 32];
        v += __shfl_xor_sync(0xffffffffu, v, 16);
        v += __shfl_xor_sync(0xffffffffu, v, 8);
        v += __shfl_xor_sync(0xffffffffu, v, 4);
        v += __shfl_xor_sync(0xffffffffu, v, 2);
        v += __shfl_xor_sync(0xffffffffu, v, 1);
        if (tid == 0) g_scratch[blockIdx.x] = v;
    }

    // Quantized write — SCALAR stores (out+1 breaks 16B alignment)
    {
        float* qbase = out + OUT_Q + (size_t)b * CDIM * HW + hw0;
        const int lane = tid & 31;
        #pragma unroll
        for (int p = 0; p < 8; p++) {
            int c = (tid >> 5) + p * 8;
            #pragma unroll
            for (int q = 0; q < 4; q++) {
                int j = lane + q * 32;
                qbase[(size_t)c * HW + j] = qs[c * TM + j];
            }
        }
    }

    // ---- fused final loss: last block reduces g_scratch ----
    __shared__ int s_last;
    __threadfence();
    if (tid == 0) {
        int old = atomicAdd(&g_count, 1);
        s_last = (old == NBLOCKS - 1) ? 1 : 0;
    }
    __syncthreads();
    if (s_last) {
        float v = g_scratch[tid] + g_scratch[tid + 256];
        v += __shfl_xor_sync(0xffffffffu, v, 16);
        v += __shfl_xor_sync(0xffffffffu, v, 8);
        v += __shfl_xor_sync(0xffffffffu, v, 4);
        v += __shfl_xor_sync(0xffffffffu, v, 2);
        v += __shfl_xor_sync(0xffffffffu, v, 1);
        if ((tid & 31) == 0) xn_s[tid >> 5] = v;
        __syncthreads();
        if (tid == 0) {
            float s = 0.f;
            #pragma unroll
            for (int w = 0; w < 8; w++) s += xn_s[w];
            out[0] = 0.25f * s / (float)ELEMS;
            g_count = 0;   // reset for next graph replay
        }
    }
}

extern "C" void kernel_launch(void* const* d_in, const int* in_sizes, int n_in,
                              void* d_out, int out_size) {
    const float* x   = (const float*)d_in[0];   // [16,64,64,64] NCHW
    const float* emb = (const float*)d_in[1];   // [1024,64]
    float* out = (float*)d_out;

    cudaFuncSetAttribute(vq_main, cudaFuncAttributeMaxDynamicSharedMemorySize,
                         SMEM_BYTES);
    vq_prep<<<KTOT / 16, 256>>>(emb);
    vq_main<<<NBLOCKS, 256, SMEM_BYTES>>>(x, emb, out);
}

// round 12
// speedup vs baseline: 1.6970x; 1.0163x over previous
#include <cuda_runtime.h>
#include <cstdint>

// Problem constants
#define BATCH   16
#define CDIM    64
#define HW      4096
#define KTOT    1024
#define NTOT    (BATCH*HW)
#define TM      128         // positions per block
#define TK      128         // codes per chunk
#define NCHUNK  (KTOT/TK)   // 8
#define NBLOCKS (NTOT/TM)   // 512
#define ELEMS   ((size_t)BATCH*CDIM*HW)   // 4194304

// Output layout: [loss(1)][quantized NCHW(4194304)][indices(65536)]
#define OUT_Q    1
#define OUT_IDX  (1 + (size_t)ELEMS)

typedef unsigned long long u64;

// Scratch (device globals)
__device__ float g_eT[CDIM * KTOT];       // embedding transposed [c][k]
__device__ float g_enorm[KTOT];           // ||e_k||^2
__device__ float g_scratch[NBLOCKS];      // per-block loss partials
__device__ int   g_count = 0;             // completion counter (self-resetting)

// ---------------- packed f32x2 helpers ----------------
__device__ __forceinline__ u64 fma2(u64 a, u64 b, u64 c) {
    u64 d;
    asm("fma.rn.f32x2 %0, %1, %2, %3;" : "=l"(d) : "l"(a), "l"(b), "l"(c));
    return d;
}
__device__ __forceinline__ u64 pack2(float a) {      // (a,a) — ALU movs, no L1
    u64 r;
    asm("mov.b64 %0, {%1, %1};" : "=l"(r) : "f"(a));
    return r;
}
__device__ __forceinline__ void unpack2(u64 v, float& lo, float& hi) {
    asm("mov.b64 {%0, %1}, %2;" : "=f"(lo), "=f"(hi) : "l"(v));
}

// ---------------- prep: transpose embedding + code norms ----------------
__global__ void vq_prep(const float* __restrict__ emb) {
    int t = threadIdx.x;
    int k = blockIdx.x * 16 + (t >> 4);
    int c = (t & 15) * 4;
    float4 v = *(const float4*)(emb + (size_t)k * CDIM + c);
    g_eT[(size_t)(c + 0) * KTOT + k] = v.x;
    g_eT[(size_t)(c + 1) * KTOT + k] = v.y;
    g_eT[(size_t)(c + 2) * KTOT + k] = v.z;
    g_eT[(size_t)(c + 3) * KTOT + k] = v.w;
    float p = v.x * v.x + v.y * v.y + v.z * v.z + v.w * v.w;
    p += __shfl_xor_sync(0xffffffffu, p, 1);
    p += __shfl_xor_sync(0xffffffffu, p, 2);
    p += __shfl_xor_sync(0xffffffffu, p, 4);
    p += __shfl_xor_sync(0xffffffffu, p, 8);
    if ((t & 15) == 0) g_enorm[k] = p;
}

// ---------------- main: distances + argmin + outputs + fused loss ----------------
// 256 threads = 16(ty) x 16(tx). Per thread: 8 j (4 natural f32x2 pairs) x 8 k.
// k set: {4tx..4tx+3} U {64+4tx..64+4tx+3}.  e packed (e,e) in REGISTERS.
// es DOUBLE-BUFFERED: copy chunk n+1 overlaps compute of chunk n; 1 sync/chunk.
// smem: xs[64][128] 32KB | es[2][64][128] 64KB | en[2][128] | xn[128] | idx[128]
#define ESTILE (CDIM*TK)
#define SMEM_BYTES (CDIM*TM*4 + 2*ESTILE*4 + 2*TK*4 + TM*4 + TM*4)

__global__ __launch_bounds__(256, 2)
void vq_main(const float* __restrict__ xin_all, const float* __restrict__ emb,
             float* __restrict__ out) {
    extern __shared__ float sm[];
    float* xs   = sm;                         // [64][128]  32KB
    float* es   = sm + CDIM * TM;             // [2][64][128] 64KB
    float* en_s = es + 2 * ESTILE;            // [2][128]
    float* xn_s = en_s + 2 * TK;              // [128]
    int*   idx_s = (int*)(xn_s + TM);         // [128]
    // overlays (phase 2)
    float* rs = xs;                           // [128][16] scores
    int*   ri = (int*)(xs + TM * 16);         // [128][16] indices
    float* qs = es;                           // [64][128] quantized tile

    const int tid = threadIdx.x;
    const int b   = blockIdx.x >> 5;
    const int hw0 = (blockIdx.x & 31) * TM;
    const float* xin = xin_all + (size_t)b * CDIM * HW + hw0;

    // Load X tile (plain, coalesced)
    #pragma unroll
    for (int p = 0; p < 8; p++) {
        int c = (tid >> 5) + p * 8;
        int j = (tid & 31) * 4;
        *(float4*)(xs + c * TM + j) = *(const float4*)(xin + (size_t)c * HW + j);
    }

    // chunk loader mapping: c row = tid>>2 (0..63), quarter = (tid&3)*32 floats
    const int lc = tid >> 2;
    const int lq = (tid & 3) * 32;

    // Preload chunk 0 into buffer 0 (overlaps with X-tile sync)
    {
        const float* src = g_eT + (size_t)lc * KTOT + 0 + lq;
        float* dst = es + lc * TK + lq;
        #pragma unroll
        for (int q = 0; q < 8; q++)
            *(float4*)(dst + q * 4) = *(const float4*)(src + q * 4);
        if (tid < TK) en_s[tid] = g_enorm[tid];
    }
    __syncthreads();

    // ||x_j||^2
    if (tid < TM) {
        float s = 0.f;
        #pragma unroll 8
        for (int c = 0; c < CDIM; c++) { float v = xs[c * TM + tid]; s += v * v; }
        xn_s[tid] = s;
    }

    const int ty = tid >> 4;   // j group (8 j's = 4 pairs)
    const int tx = tid & 15;   // k group
    float best[8];
    int   bidx[8];
    #pragma unroll
    for (int jj = 0; jj < 8; jj++) { best[jj] = 3.4e38f; bidx[jj] = 0x7fffffff; }

    for (int chunk = 0; chunk < NCHUNK; chunk++) {
        const int kbase = chunk * TK;
        const float* cur = es + (chunk & 1) * ESTILE;
        const float* enc = en_s + (chunk & 1) * TK;

        // Prefetch next chunk into the other buffer (overlaps compute below)
        if (chunk < NCHUNK - 1) {
            float* nxt = es + ((chunk + 1) & 1) * ESTILE;
            const float* src = g_eT + (size_t)lc * KTOT + (kbase + TK) + lq;
            float* dst = nxt + lc * TK + lq;
            #pragma unroll
            for (int q = 0; q < 8; q++)
                *(float4*)(dst + q * 4) = *(const float4*)(src + q * 4);
            if (tid < TK) en_s[((chunk + 1) & 1) * TK + tid] = g_enorm[kbase + TK + tid];
        }

        u64 acc[4][8];
        #pragma unroll
        for (int jp = 0; jp < 4; jp++)
            #pragma unroll
            for (int m = 0; m < 8; m++) acc[jp][m] = 0ull;

        #pragma unroll 4
        for (int c = 0; c < CDIM; c++) {
            const ulonglong2* xp = (const ulonglong2*)(xs + c * TM + ty * 8);
            ulonglong2 xa = xp[0], xb = xp[1];
            u64 xj[4] = {xa.x, xa.y, xb.x, xb.y};   // natural j-pairs
            float4 ea = *(const float4*)(cur + c * TK + 4 * tx);
            float4 eb = *(const float4*)(cur + c * TK + 64 + 4 * tx);
            u64 ep[8];
            ep[0] = pack2(ea.x); ep[1] = pack2(ea.y);
            ep[2] = pack2(ea.z); ep[3] = pack2(ea.w);
            ep[4] = pack2(eb.x); ep[5] = pack2(eb.y);
            ep[6] = pack2(eb.z); ep[7] = pack2(eb.w);
            #pragma unroll
            for (int m = 0; m < 8; m++) {
                acc[0][m] = fma2(xj[0], ep[m], acc[0][m]);
                acc[1][m] = fma2(xj[1], ep[m], acc[1][m]);
                acc[2][m] = fma2(xj[2], ep[m], acc[2][m]);
                acc[3][m] = fma2(xj[3], ep[m], acc[3][m]);
            }
        }

        // scores: ||e||^2 - 2 x.e ; m ascending => per-thread k ascending
        #pragma unroll
        for (int m = 0; m < 8; m++) {
            const int klocal = (m < 4) ? (4 * tx + m) : (64 + 4 * tx + m - 4);
            const int k0 = kbase + klocal;
            const float en = enc[klocal];
            #pragma unroll
            for (int jp = 0; jp < 4; jp++) {
                float lo, hi;
                unpack2(acc[jp][m], lo, hi);
                float s0 = en - (lo + lo);   // j = ty*8 + 2*jp
                float s1 = en - (hi + hi);   // j = ty*8 + 2*jp + 1
                if (s0 < best[2 * jp])     { best[2 * jp] = s0;     bidx[2 * jp] = k0; }
                if (s1 < best[2 * jp + 1]) { best[2 * jp + 1] = s1; bidx[2 * jp + 1] = k0; }
            }
        }

        __syncthreads();   // next buffer fully written; this buffer free
    }

    // overlays safe after final sync
    #pragma unroll
    for (int jj = 0; jj < 8; jj++) {
        int j = ty * 8 + jj;
        rs[j * 16 + tx] = best[jj];
        ri[j * 16 + tx] = bidx[jj];
    }
    __syncthreads();

    if (tid < TM) {
        float bs = rs[tid * 16];
        int   bk = ri[tid * 16];
        #pragma unroll
        for (int t = 1; t < 16; t++) {
            float s = rs[tid * 16 + t];
            int   k = ri[tid * 16 + t];
            if (s < bs || (s == bs && k < bk)) { bs = s; bk = k; }
        }
        idx_s[tid] = bk;
        out[OUT_IDX + (size_t)b * HW + hw0 + tid] = (float)bk;
        xn_s[tid] = bs + xn_s[tid];   // dist = score + ||x||^2
    }
    __syncthreads();

    // Gather emb rows (contiguous 256B) into qs, transposed to [c][j]
    {
        const int jq = tid >> 1;
        const int c0 = (tid & 1) * 32;
        const int kq = idx_s[jq];
        const float4* erow = (const float4*)(emb + (size_t)kq * CDIM + c0);
        #pragma unroll
        for (int q = 0; q < 8; q++) {
            float4 v = erow[q];
            int c = c0 + q * 4;
            qs[(c + 0) * TM + jq] = v.x;
            qs[(c + 1) * TM + jq] = v.y;
            qs[(c + 2) * TM + jq] = v.z;
            qs[(c + 3) * TM + jq] = v.w;
        }
    }
    if (tid < 64) xn_s[tid] += xn_s[tid + 64];
    __syncthreads();

    if (tid < 32) {
        float v = xn_s[tid] + xn_s[tid + 32];
        v += __shfl_xor_sync(0xffffffffu, v, 16);
        v += __shfl_xor_sync(0xffffffffu, v, 8);
        v += __shfl_xor_sync(0xffffffffu, v, 4);
        v += __shfl_xor_sync(0xffffffffu, v, 2);
        v += __shfl_xor_sync(0xffffffffu, v, 1);
        if (tid == 0) g_scratch[blockIdx.x] = v;
    }

    // Quantized write — SCALAR stores (out+1 breaks 16B alignment)
    {
        float* qbase = out + OUT_Q + (size_t)b * CDIM * HW + hw0;
        const int lane = tid & 31;
        #pragma unroll
        for (int p = 0; p < 8; p++) {
            int c = (tid >> 5) + p * 8;
            #pragma unroll
            for (int q = 0; q < 4; q++) {
                int j = lane + q * 32;
                qbase[(size_t)c * HW + j] = qs[c * TM + j];
            }
        }
    }

    // ---- fused final loss: last block reduces g_scratch ----
    __shared__ int s_last;
    __threadfence();
    if (tid == 0) {
        int old = atomicAdd(&g_count, 1);
        s_last = (old == NBLOCKS - 1) ? 1 : 0;
    }
    __syncthreads();
    if (s_last) {
        float v = g_scratch[tid] + g_scratch[tid + 256];
        v += __shfl_xor_sync(0xffffffffu, v, 16);
        v += __shfl_xor_sync(0xffffffffu, v, 8);
        v += __shfl_xor_sync(0xffffffffu, v, 4);
        v += __shfl_xor_sync(0xffffffffu, v, 2);
        v += __shfl_xor_sync(0xffffffffu, v, 1);
        if ((tid & 31) == 0) xn_s[tid >> 5] = v;
        __syncthreads();
        if (tid == 0) {
            float s = 0.f;
            #pragma unroll
            for (int w = 0; w < 8; w++) s += xn_s[w];
            out[0] = 0.25f * s / (float)ELEMS;
            g_count = 0;   // reset for next graph replay
        }
    }
}

extern "C" void kernel_launch(void* const* d_in, const int* in_sizes, int n_in,
                              void* d_out, int out_size) {
    const float* x   = (const float*)d_in[0];   // [16,64,64,64] NCHW
    const float* emb = (const float*)d_in[1];   // [1024,64]
    float* out = (float*)d_out;

    cudaFuncSetAttribute(vq_main, cudaFuncAttributeMaxDynamicSharedMemorySize,
                         SMEM_BYTES);
    vq_prep<<<KTOT / 16, 256>>>(emb);
    vq_main<<<NBLOCKS, 256, SMEM_BYTES>>>(x, emb, out);
}

// round 15
// speedup vs baseline: 1.7119x; 1.0088x over previous
#include <cuda_runtime.h>
#include <cuda_bf16.h>
#include <cstdint>

// Problem constants
#define BATCH   16
#define CDIM    64
#define HW      4096
#define KTOT    1024
#define NTOT    (BATCH*HW)
#define TM      128         // positions per block (M)
#define TN      128         // codes per chunk (N)
#define NCHUNK  (KTOT/TN)   // 8
#define NBLOCKS (NTOT/TM)   // 512
#define ELEMS   ((size_t)BATCH*CDIM*HW)   // 4194304

// Output layout: [loss(1)][quantized NCHW(4194304)][indices(65536)]
#define OUT_Q    1
#define OUT_IDX  (1 + (size_t)ELEMS)

// SMEM layout (bytes): A h/m/l [128j][64c] bf16; B h/m/l [128n][64c] bf16
#define A_TILE   16384
#define B_TILE   16384
#define OFF_A    0
#define OFF_B    (3*A_TILE)             // 49152
#define OFF_EN   (OFF_B + 3*B_TILE)     // 98304
#define OFF_XN   (OFF_EN + KTOT*4)      // 102400
#define OFF_IDXS (OFF_XN + TM*4)        // 102912
#define SMEM_TOTAL (OFF_IDXS + TM*4)    // 103424

#define SWZ(o) ((o) ^ (((o) >> 3) & 0x70))

// Device globals
__device__ __align__(16) __nv_bfloat16 g_eh[KTOT*CDIM];
__device__ __align__(16) __nv_bfloat16 g_em[KTOT*CDIM];
__device__ __align__(16) __nv_bfloat16 g_el[KTOT*CDIM];
__device__ __align__(16) float g_enorm[KTOT];
__device__ float g_scratch[NBLOCKS];
__device__ int   g_count = 0;

// ---------------- helpers ----------------
__device__ __forceinline__ uint32_t smem_u32(const void* p) {
    uint32_t a;
    asm("{ .reg .u64 t; cvta.to.shared.u64 t, %1; cvt.u32.u64 %0, t; }"
        : "=r"(a) : "l"(p));
    return a;
}
__device__ __forceinline__ void ldsm4(uint32_t* r, uint32_t addr) {
    asm volatile("ldmatrix.sync.aligned.m8n8.x4.shared.b16 {%0,%1,%2,%3}, [%4];"
                 : "=r"(r[0]), "=r"(r[1]), "=r"(r[2]), "=r"(r[3]) : "r"(addr));
}
__device__ __forceinline__ void mma_bf16(float* c, const uint32_t* a,
                                         uint32_t b0, uint32_t b1) {
    asm volatile(
        "mma.sync.aligned.m16n8k16.row.col.f32.bf16.bf16.f32 "
        "{%0,%1,%2,%3}, {%4,%5,%6,%7}, {%8,%9}, {%0,%1,%2,%3};"
        : "+f"(c[0]), "+f"(c[1]), "+f"(c[2]), "+f"(c[3])
        : "r"(a[0]), "r"(a[1]), "r"(a[2]), "r"(a[3]), "r"(b0), "r"(b1));
}

// ---------------- prep: bf16 3-split of embedding + norms ----------------
__global__ void vq_prep(const float* __restrict__ emb) {
    int t = threadIdx.x;
    int k = blockIdx.x * 16 + (t >> 4);
    int c = (t & 15) * 4;
    float4 v = *(const float4*)(emb + (size_t)k * CDIM + c);
    float vv[4] = {v.x, v.y, v.z, v.w};
    #pragma unroll
    for (int i = 0; i < 4; i++) {
        float x = vv[i];
        __nv_bfloat16 h = __float2bfloat16(x);
        float r = x - __bfloat162float(h);
        __nv_bfloat16 m = __float2bfloat16(r);
        float r2 = r - __bfloat162float(m);
        __nv_bfloat16 l = __float2bfloat16(r2);
        g_eh[(size_t)k * CDIM + c + i] = h;
        g_em[(size_t)k * CDIM + c + i] = m;
        g_el[(size_t)k * CDIM + c + i] = l;
    }
    float p = v.x * v.x + v.y * v.y + v.z * v.z + v.w * v.w;
    p += __shfl_xor_sync(0xffffffffu, p, 1);
    p += __shfl_xor_sync(0xffffffffu, p, 2);
    p += __shfl_xor_sync(0xffffffffu, p, 4);
    p += __shfl_xor_sync(0xffffffffu, p, 8);
    if ((t & 15) == 0) g_enorm[k] = p;
}

// ---------------- main: HMMA bf16 3-split GEMM + argmin ----------------
__global__ __launch_bounds__(256, 2)
void vq_main(const float* __restrict__ xin_all, const float* __restrict__ emb,
             float* __restrict__ out) {
    extern __shared__ char smem[];
    const uint32_t sb = smem_u32(smem);
    float* xs    = (float*)(smem + OFF_B);     // fp32 staging in B region
    float* en_s  = (float*)(smem + OFF_EN);
    float* xn_s  = (float*)(smem + OFF_XN);
    int*   idx_s = (int*)(smem + OFF_IDXS);
    float* qs    = (float*)(smem + OFF_B);     // quantized staging (post-loop)

    const int tid = threadIdx.x;
    const int wid = tid >> 5;
    const int lid = tid & 31;
    const int b   = blockIdx.x >> 5;
    const int hw0 = (blockIdx.x & 31) * TM;
    const float* xin = xin_all + (size_t)b * CDIM * HW + hw0;

    // Load X tile fp32 [c][j] (coalesced) + enorm (full 1024)
    #pragma unroll
    for (int p = 0; p < 8; p++) {
        int c = (tid >> 5) + p * 8;
        int j = (tid & 31) * 4;
        *(float4*)(xs + c * TM + j) = *(const float4*)(xin + (size_t)c * HW + j);
    }
    *((float4*)en_s + tid) = *((const float4*)g_enorm + tid);
    __syncthreads();

    // Convert X -> 3 bf16 A tiles (swizzled) + fused ||x||^2
    {
        const int j  = tid >> 1;
        const int ch = (tid & 1) * 32;
        float nacc = 0.f;
        #pragma unroll
        for (int cc = 0; cc < 32; cc += 2) {
            int c = ch + cc;
            float v0 = xs[c * TM + j];
            float v1 = xs[(c + 1) * TM + j];
            nacc += v0 * v0 + v1 * v1;
            __nv_bfloat16 h0 = __float2bfloat16(v0);
            float r0 = v0 - __bfloat162float(h0);
            __nv_bfloat16 m0 = __float2bfloat16(r0);
            __nv_bfloat16 l0 = __float2bfloat16(r0 - __bfloat162float(m0));
            __nv_bfloat16 h1 = __float2bfloat16(v1);
            float r1 = v1 - __bfloat162float(h1);
            __nv_bfloat16 m1 = __float2bfloat16(r1);
            __nv_bfloat16 l1 = __float2bfloat16(r1 - __bfloat162float(m1));
            uint32_t off = SWZ((uint32_t)(j * 128 + c * 2));
            uint32_t ph = ((uint32_t)__bfloat16_as_ushort(h1) << 16) | __bfloat16_as_ushort(h0);
            uint32_t pm = ((uint32_t)__bfloat16_as_ushort(m1) << 16) | __bfloat16_as_ushort(m0);
            uint32_t pl = ((uint32_t)__bfloat16_as_ushort(l1) << 16) | __bfloat16_as_ushort(l0);
            *(uint32_t*)(smem + OFF_A + off)              = ph;
            *(uint32_t*)(smem + OFF_A + A_TILE + off)     = pm;
            *(uint32_t*)(smem + OFF_A + 2 * A_TILE + off) = pl;
        }
        nacc += __shfl_xor_sync(0xffffffffu, nacc, 1);
        if ((tid & 1) == 0) xn_s[j] = nacc;
    }
    __syncthreads();   // A tiles ready; xs (B region) free

    // ldmatrix lane address components
    const int wbase = wid * 16;
    const int lt = lid >> 3, lr = lid & 7;
    const int rowA  = wbase + lr + 8 * (lt & 1);
    const int colA8 = (lt >> 1) * 8;
    const int rowB  = lr + 8 * (lt >> 1);
    const int colB8 = (lt & 1) * 8;

    float best0 = 3.4e38f, best1 = 3.4e38f;
    int   bidx0 = 0x7fffffff, bidx1 = 0x7fffffff;

    static const int pa[6] = {0, 0, 1, 1, 0, 2};
    static const int pb[6] = {0, 1, 0, 1, 2, 0};

    for (int chunk = 0; chunk < NCHUNK; chunk++) {
        const int kbase = chunk * TN;

        __syncthreads();   // all warps done reading previous B
        {
            const char* s0 = (const char*)(g_eh + (size_t)kbase * CDIM);
            const char* s1 = (const char*)(g_em + (size_t)kbase * CDIM);
            const char* s2 = (const char*)(g_el + (size_t)kbase * CDIM);
            #pragma unroll
            for (int i = 0; i < 4; i++) {
                uint32_t u = (uint32_t)(tid + 256 * i) * 16;
                uint32_t d = SWZ(u);
                *(uint4*)(smem + OFF_B + d)              = *(const uint4*)(s0 + u);
                *(uint4*)(smem + OFF_B + B_TILE + d)     = *(const uint4*)(s1 + u);
                *(uint4*)(smem + OFF_B + 2 * B_TILE + d) = *(const uint4*)(s2 + u);
            }
        }
        __syncthreads();

        #pragma unroll
        for (int half = 0; half < 2; half++) {
            float acc[32];
            #pragma unroll
            for (int i = 0; i < 32; i++) acc[i] = 0.f;

            #pragma unroll
            for (int p = 0; p < 6; p++) {
                const uint32_t abase = sb + OFF_A + pa[p] * A_TILE;
                const uint32_t bbase = sb + OFF_B + pb[p] * B_TILE;
                #pragma unroll
                for (int ks = 0; ks < 4; ks++) {
                    uint32_t afrag[4];
                    ldsm4(afrag, abase + SWZ((uint32_t)(rowA * 128 + ks * 32 + colA8 * 2)));
                    #pragma unroll
                    for (int ntp = 0; ntp < 4; ntp++) {
                        const int nb = half * 64 + ntp * 16;
                        uint32_t bfrag[4];
                        ldsm4(bfrag, bbase + SWZ((uint32_t)((nb + rowB) * 128 + ks * 32 + colB8 * 2)));
                        mma_bf16(&acc[ntp * 8],     afrag, bfrag[0], bfrag[1]);
                        mma_bf16(&acc[ntp * 8 + 4], afrag, bfrag[2], bfrag[3]);
                    }
                }
            }

            // scores: ||e||^2 - 2 dot ; nt ascending => k ascending (first-idx ties)
            #pragma unroll
            for (int nt = 0; nt < 8; nt++) {
                const int k = kbase + half * 64 + nt * 8 + 2 * (lid & 3);
                const float* ac = &acc[nt * 4];
                float e0 = en_s[k], e1 = en_s[k + 1];
                float s0 = e0 - (ac[0] + ac[0]);
                float s1 = e1 - (ac[1] + ac[1]);
                float s2 = e0 - (ac[2] + ac[2]);
                float s3 = e1 - (ac[3] + ac[3]);
                if (s0 < best0) { best0 = s0; bidx0 = k; }
                if (s1 < best0) { best0 = s1; bidx0 = k + 1; }
                if (s2 < best1) { best1 = s2; bidx1 = k; }
                if (s3 < best1) { best1 = s3; bidx1 = k + 1; }
            }
        }
    }

    // quad reduction (lanes sharing lid>>2 hold the same j rows)
    #pragma unroll
    for (int d = 1; d <= 2; d <<= 1) {
        float os = __shfl_xor_sync(0xffffffffu, best0, d);
        int   ok = __shfl_xor_sync(0xffffffffu, bidx0, d);
        if (os < best0 || (os == best0 && ok < bidx0)) { best0 = os; bidx0 = ok; }
        os = __shfl_xor_sync(0xffffffffu, best1, d);
        ok = __shfl_xor_sync(0xffffffffu, bidx1, d);
        if (os < best1 || (os == best1 && ok < bidx1)) { best1 = os; bidx1 = ok; }
    }
    if ((lid & 3) == 0) {
        int j0 = wbase + (lid >> 2);
        int j1 = j0 + 8;
        idx_s[j0] = bidx0;
        idx_s[j1] = bidx1;
        out[OUT_IDX + (size_t)b * HW + hw0 + j0] = (float)bidx0;
        out[OUT_IDX + (size_t)b * HW + hw0 + j1] = (float)bidx1;
        xn_s[j0] = best0 + xn_s[j0];   // dist = score + ||x||^2
        xn_s[j1] = best1 + xn_s[j1];
    }
    __syncthreads();

    // Gather emb rows (contiguous 256B) into qs [c][j]
    {
        const int jq = tid >> 1;
        const int c0 = (tid & 1) * 32;
        const int kq = idx_s[jq];
        const float4* erow = (const float4*)(emb + (size_t)kq * CDIM + c0);
        #pragma unroll
        for (int q = 0; q < 8; q++) {
            float4 v = erow[q];
            int c = c0 + q * 4;
            qs[(c + 0) * TM + jq] = v.x;
            qs[(c + 1) * TM + jq] = v.y;
            qs[(c + 2) * TM + jq] = v.z;
            qs[(c + 3) * TM + jq] = v.w;
        }
    }
    if (tid < 64) xn_s[tid] += xn_s[tid + 64];
    __syncthreads();

    if (tid < 32) {
        float v = xn_s[tid] + xn_s[tid + 32];
        v += __shfl_xor_sync(0xffffffffu, v, 16);
        v += __shfl_xor_sync(0xffffffffu, v, 8);
        v += __shfl_xor_sync(0xffffffffu, v, 4);
        v += __shfl_xor_sync(0xffffffffu, v, 2);
        v += __shfl_xor_sync(0xffffffffu, v, 1);
        if (tid == 0) g_scratch[blockIdx.x] = v;
    }

    // Quantized write — SCALAR stores (out+1 breaks 16B alignment)
    {
        float* qbase = out + OUT_Q + (size_t)b * CDIM * HW + hw0;
        const int lane = tid & 31;
        #pragma unroll
        for (int p = 0; p < 8; p++) {
            int c = (tid >> 5) + p * 8;
            #pragma unroll
            for (int q = 0; q < 4; q++) {
                int j = lane + q * 32;
                qbase[(size_t)c * HW + j] = qs[c * TM + j];
            }
        }
    }

    // ---- fused final loss ----
    __shared__ int s_last;
    __threadfence();
    if (tid == 0) {
        int old = atomicAdd(&g_count, 1);
        s_last = (old == NBLOCKS - 1) ? 1 : 0;
    }
    __syncthreads();
    if (s_last) {
        float v = g_scratch[tid] + g_scratch[tid + 256];
        v += __shfl_xor_sync(0xffffffffu, v, 16);
        v += __shfl_xor_sync(0xffffffffu, v, 8);
        v += __shfl_xor_sync(0xffffffffu, v, 4);
        v += __shfl_xor_sync(0xffffffffu, v, 2);
        v += __shfl_xor_sync(0xffffffffu, v, 1);
        if ((tid & 31) == 0) xn_s[tid >> 5] = v;
        __syncthreads();
        if (tid == 0) {
            float s = 0.f;
            #pragma unroll
            for (int w = 0; w < 8; w++) s += xn_s[w];
            out[0] = 0.25f * s / (float)ELEMS;
            g_count = 0;
        }
    }
}

extern "C" void kernel_launch(void* const* d_in, const int* in_sizes, int n_in,
                              void* d_out, int out_size) {
    const float* x   = (const float*)d_in[0];   // [16,64,64,64] NCHW
    const float* emb = (const float*)d_in[1];   // [1024,64]
    float* out = (float*)d_out;

    cudaFuncSetAttribute(vq_main, cudaFuncAttributeMaxDynamicSharedMemorySize,
                         SMEM_TOTAL);
    vq_prep<<<KTOT / 16, 256>>>(emb);
    vq_main<<<NBLOCKS, 256, SMEM_TOTAL>>>(x, emb, out);
}

// round 16
// speedup vs baseline: 2.6651x; 1.5568x over previous
#include <cuda_runtime.h>
#include <cuda_bf16.h>
#include <cstdint>

// Problem constants
#define BATCH   16
#define CDIM    64
#define HW      4096
#define KTOT    1024
#define NTOT    (BATCH*HW)
#define TM      128         // positions per block (M)
#define TN      128         // codes per chunk (N)
#define NCHUNK  (KTOT/TN)   // 8
#define NBLOCKS (NTOT/TM)   // 512
#define ELEMS   ((size_t)BATCH*CDIM*HW)   // 4194304

// Output layout: [loss(1)][quantized NCHW(4194304)][indices(65536)]
#define OUT_Q    1
#define OUT_IDX  (1 + (size_t)ELEMS)

// SMEM layout (bytes): A h/m/l [128j][64c] bf16; B h/m/l [128n][64c] bf16
#define A_TILE   16384
#define B_TILE   16384
#define OFF_A    0
#define OFF_B    (3*A_TILE)             // 49152
#define OFF_EN   (OFF_B + 3*B_TILE)     // 98304
#define OFF_XN   (OFF_EN + KTOT*4)      // 102400
#define OFF_IDXS (OFF_XN + TM*4)        // 102912
#define SMEM_TOTAL (OFF_IDXS + TM*4)    // 103424

#define SWZ(o) ((o) ^ (((o) >> 3) & 0x70))

// Device globals
__device__ __align__(16) __nv_bfloat16 g_eh[KTOT*CDIM];
__device__ __align__(16) __nv_bfloat16 g_em[KTOT*CDIM];
__device__ __align__(16) __nv_bfloat16 g_el[KTOT*CDIM];
__device__ __align__(16) float g_enorm[KTOT];
__device__ float g_scratch[NBLOCKS];
__device__ int   g_count = 0;

// ---------------- helpers ----------------
__device__ __forceinline__ uint32_t smem_u32(const void* p) {
    uint32_t a;
    asm("{ .reg .u64 t; cvta.to.shared.u64 t, %1; cvt.u32.u64 %0, t; }"
        : "=r"(a) : "l"(p));
    return a;
}
__device__ __forceinline__ void ldsm4(uint32_t* r, uint32_t addr) {
    asm volatile("ldmatrix.sync.aligned.m8n8.x4.shared.b16 {%0,%1,%2,%3}, [%4];"
                 : "=r"(r[0]), "=r"(r[1]), "=r"(r[2]), "=r"(r[3]) : "r"(addr));
}
__device__ __forceinline__ void mma_bf16(float* c, const uint32_t* a,
                                         uint32_t b0, uint32_t b1) {
    asm volatile(
        "mma.sync.aligned.m16n8k16.row.col.f32.bf16.bf16.f32 "
        "{%0,%1,%2,%3}, {%4,%5,%6,%7}, {%8,%9}, {%0,%1,%2,%3};"
        : "+f"(c[0]), "+f"(c[1]), "+f"(c[2]), "+f"(c[3])
        : "r"(a[0]), "r"(a[1]), "r"(a[2]), "r"(a[3]), "r"(b0), "r"(b1));
}

// ---------------- prep: bf16 3-split of embedding + norms ----------------
__global__ void vq_prep(const float* __restrict__ emb) {
    int t = threadIdx.x;
    int k = blockIdx.x * 16 + (t >> 4);
    int c = (t & 15) * 4;
    float4 v = *(const float4*)(emb + (size_t)k * CDIM + c);
    float vv[4] = {v.x, v.y, v.z, v.w};
    #pragma unroll
    for (int i = 0; i < 4; i++) {
        float x = vv[i];
        __nv_bfloat16 h = __float2bfloat16(x);
        float r = x - __bfloat162float(h);
        __nv_bfloat16 m = __float2bfloat16(r);
        float r2 = r - __bfloat162float(m);
        __nv_bfloat16 l = __float2bfloat16(r2);
        g_eh[(size_t)k * CDIM + c + i] = h;
        g_em[(size_t)k * CDIM + c + i] = m;
        g_el[(size_t)k * CDIM + c + i] = l;
    }
    float p = v.x * v.x + v.y * v.y + v.z * v.z + v.w * v.w;
    p += __shfl_xor_sync(0xffffffffu, p, 1);
    p += __shfl_xor_sync(0xffffffffu, p, 2);
    p += __shfl_xor_sync(0xffffffffu, p, 4);
    p += __shfl_xor_sync(0xffffffffu, p, 8);
    if ((t & 15) == 0) g_enorm[k] = p;
}

// ---------------- main: HMMA bf16 3-split GEMM + argmin ----------------
// A fragments (all 3 splits, all 4 k-steps) hoisted to registers before the
// chunk loop — zero A-side LDSM in the mainloop. Per (ks,ntp): 3 B ldsm4 +
// 12 MMAs (hh, hm, mh, mm, hl, lh).
__global__ __launch_bounds__(256, 2)
void vq_main(const float* __restrict__ xin_all, const float* __restrict__ emb,
             float* __restrict__ out) {
    extern __shared__ char smem[];
    const uint32_t sb = smem_u32(smem);
    float* xs    = (float*)(smem + OFF_B);     // fp32 staging in B region
    float* en_s  = (float*)(smem + OFF_EN);
    float* xn_s  = (float*)(smem + OFF_XN);
    int*   idx_s = (int*)(smem + OFF_IDXS);
    float* qs    = (float*)(smem + OFF_B);     // quantized staging (post-loop)

    const int tid = threadIdx.x;
    const int wid = tid >> 5;
    const int lid = tid & 31;
    const int b   = blockIdx.x >> 5;
    const int hw0 = (blockIdx.x & 31) * TM;
    const float* xin = xin_all + (size_t)b * CDIM * HW + hw0;

    // Load X tile fp32 [c][j] (coalesced) + enorm (full 1024)
    #pragma unroll
    for (int p = 0; p < 8; p++) {
        int c = (tid >> 5) + p * 8;
        int j = (tid & 31) * 4;
        *(float4*)(xs + c * TM + j) = *(const float4*)(xin + (size_t)c * HW + j);
    }
    *((float4*)en_s + tid) = *((const float4*)g_enorm + tid);
    __syncthreads();

    // Convert X -> 3 bf16 A tiles (swizzled) + fused ||x||^2
    {
        const int j  = tid >> 1;
        const int ch = (tid & 1) * 32;
        float nacc = 0.f;
        #pragma unroll
        for (int cc = 0; cc < 32; cc += 2) {
            int c = ch + cc;
            float v0 = xs[c * TM + j];
            float v1 = xs[(c + 1) * TM + j];
            nacc += v0 * v0 + v1 * v1;
            __nv_bfloat16 h0 = __float2bfloat16(v0);
            float r0 = v0 - __bfloat162float(h0);
            __nv_bfloat16 m0 = __float2bfloat16(r0);
            __nv_bfloat16 l0 = __float2bfloat16(r0 - __bfloat162float(m0));
            __nv_bfloat16 h1 = __float2bfloat16(v1);
            float r1 = v1 - __bfloat162float(h1);
            __nv_bfloat16 m1 = __float2bfloat16(r1);
            __nv_bfloat16 l1 = __float2bfloat16(r1 - __bfloat162float(m1));
            uint32_t off = SWZ((uint32_t)(j * 128 + c * 2));
            uint32_t ph = ((uint32_t)__bfloat16_as_ushort(h1) << 16) | __bfloat16_as_ushort(h0);
            uint32_t pm = ((uint32_t)__bfloat16_as_ushort(m1) << 16) | __bfloat16_as_ushort(m0);
            uint32_t pl = ((uint32_t)__bfloat16_as_ushort(l1) << 16) | __bfloat16_as_ushort(l0);
            *(uint32_t*)(smem + OFF_A + off)              = ph;
            *(uint32_t*)(smem + OFF_A + A_TILE + off)     = pm;
            *(uint32_t*)(smem + OFF_A + 2 * A_TILE + off) = pl;
        }
        nacc += __shfl_xor_sync(0xffffffffu, nacc, 1);
        if ((tid & 1) == 0) xn_s[j] = nacc;
    }
    __syncthreads();   // A tiles ready; xs (B region) free

    // ldmatrix lane address components
    const int wbase = wid * 16;
    const int lt = lid >> 3, lr = lid & 7;
    const int rowA  = wbase + lr + 8 * (lt & 1);
    const int colA8 = (lt >> 1) * 8;
    const int rowB  = lr + 8 * (lt >> 1);
    const int colB8 = (lt & 1) * 8;

    // Hoist ALL A fragments (3 splits x 4 k-steps) — chunk-invariant
    uint32_t aH[4][4], aM[4][4], aL[4][4];
    #pragma unroll
    for (int ks = 0; ks < 4; ks++) {
        uint32_t ao = SWZ((uint32_t)(rowA * 128 + ks * 32 + colA8 * 2));
        ldsm4(aH[ks], sb + OFF_A + ao);
        ldsm4(aM[ks], sb + OFF_A + A_TILE + ao);
        ldsm4(aL[ks], sb + OFF_A + 2 * A_TILE + ao);
    }

    float best0 = 3.4e38f, best1 = 3.4e38f;
    int   bidx0 = 0x7fffffff, bidx1 = 0x7fffffff;

    for (int chunk = 0; chunk < NCHUNK; chunk++) {
        const int kbase = chunk * TN;

        __syncthreads();   // all warps done reading previous B
        {
            const char* s0 = (const char*)(g_eh + (size_t)kbase * CDIM);
            const char* s1 = (const char*)(g_em + (size_t)kbase * CDIM);
            const char* s2 = (const char*)(g_el + (size_t)kbase * CDIM);
            #pragma unroll
            for (int i = 0; i < 4; i++) {
                uint32_t u = (uint32_t)(tid + 256 * i) * 16;
                uint32_t d = SWZ(u);
                *(uint4*)(smem + OFF_B + d)              = *(const uint4*)(s0 + u);
                *(uint4*)(smem + OFF_B + B_TILE + d)     = *(const uint4*)(s1 + u);
                *(uint4*)(smem + OFF_B + 2 * B_TILE + d) = *(const uint4*)(s2 + u);
            }
        }
        __syncthreads();

        #pragma unroll
        for (int half = 0; half < 2; half++) {
            float acc[32];
            #pragma unroll
            for (int i = 0; i < 32; i++) acc[i] = 0.f;

            #pragma unroll
            for (int ks = 0; ks < 4; ks++) {
                #pragma unroll
                for (int ntp = 0; ntp < 4; ntp++) {
                    const int nb = half * 64 + ntp * 16;
                    uint32_t bo = SWZ((uint32_t)((nb + rowB) * 128 + ks * 32 + colB8 * 2));
                    uint32_t bh[4], bm[4], bl[4];
                    ldsm4(bh, sb + OFF_B + bo);
                    ldsm4(bm, sb + OFF_B + B_TILE + bo);
                    ldsm4(bl, sb + OFF_B + 2 * B_TILE + bo);
                    float* a0 = &acc[ntp * 8];
                    float* a1 = &acc[ntp * 8 + 4];
                    mma_bf16(a0, aH[ks], bh[0], bh[1]);  // hh
                    mma_bf16(a1, aH[ks], bh[2], bh[3]);
                    mma_bf16(a0, aH[ks], bm[0], bm[1]);  // hm
                    mma_bf16(a1, aH[ks], bm[2], bm[3]);
                    mma_bf16(a0, aM[ks], bh[0], bh[1]);  // mh
                    mma_bf16(a1, aM[ks], bh[2], bh[3]);
                    mma_bf16(a0, aM[ks], bm[0], bm[1]);  // mm
                    mma_bf16(a1, aM[ks], bm[2], bm[3]);
                    mma_bf16(a0, aH[ks], bl[0], bl[1]);  // hl
                    mma_bf16(a1, aH[ks], bl[2], bl[3]);
                    mma_bf16(a0, aL[ks], bh[0], bh[1]);  // lh
                    mma_bf16(a1, aL[ks], bh[2], bh[3]);
                }
            }

            // scores: ||e||^2 - 2 dot ; nt ascending => k ascending (first-idx ties)
            #pragma unroll
            for (int nt = 0; nt < 8; nt++) {
                const int k = kbase + half * 64 + nt * 8 + 2 * (lid & 3);
                const float* ac = &acc[nt * 4];
                float e0 = en_s[k], e1 = en_s[k + 1];
                float s0 = e0 - (ac[0] + ac[0]);
                float s1 = e1 - (ac[1] + ac[1]);
                float s2 = e0 - (ac[2] + ac[2]);
                float s3 = e1 - (ac[3] + ac[3]);
                if (s0 < best0) { best0 = s0; bidx0 = k; }
                if (s1 < best0) { best0 = s1; bidx0 = k + 1; }
                if (s2 < best1) { best1 = s2; bidx1 = k; }
                if (s3 < best1) { best1 = s3; bidx1 = k + 1; }
            }
        }
    }

    // quad reduction (lanes sharing lid>>2 hold the same j rows)
    #pragma unroll
    for (int d = 1; d <= 2; d <<= 1) {
        float os = __shfl_xor_sync(0xffffffffu, best0, d);
        int   ok = __shfl_xor_sync(0xffffffffu, bidx0, d);
        if (os < best0 || (os == best0 && ok < bidx0)) { best0 = os; bidx0 = ok; }
        os = __shfl_xor_sync(0xffffffffu, best1, d);
        ok = __shfl_xor_sync(0xffffffffu, bidx1, d);
        if (os < best1 || (os == best1 && ok < bidx1)) { best1 = os; bidx1 = ok; }
    }
    if ((lid & 3) == 0) {
        int j0 = wbase + (lid >> 2);
        int j1 = j0 + 8;
        idx_s[j0] = bidx0;
        idx_s[j1] = bidx1;
        out[OUT_IDX + (size_t)b * HW + hw0 + j0] = (float)bidx0;
        out[OUT_IDX + (size_t)b * HW + hw0 + j1] = (float)bidx1;
        xn_s[j0] = best0 + xn_s[j0];   // dist = score + ||x||^2
        xn_s[j1] = best1 + xn_s[j1];
    }
    __syncthreads();

    // Gather emb rows (contiguous 256B) into qs [c][j]
    {
        const int jq = tid >> 1;
        const int c0 = (tid & 1) * 32;
        const int kq = idx_s[jq];
        const float4* erow = (const float4*)(emb + (size_t)kq * CDIM + c0);
        #pragma unroll
        for (int q = 0; q < 8; q++) {
            float4 v = erow[q];
            int c = c0 + q * 4;
            qs[(c + 0) * TM + jq] = v.x;
            qs[(c + 1) * TM + jq] = v.y;
            qs[(c + 2) * TM + jq] = v.z;
            qs[(c + 3) * TM + jq] = v.w;
        }
    }
    if (tid < 64) xn_s[tid] += xn_s[tid + 64];
    __syncthreads();

    if (tid < 32) {
        float v = xn_s[tid] + xn_s[tid + 32];
        v += __shfl_xor_sync(0xffffffffu, v, 16);
        v += __shfl_xor_sync(0xffffffffu, v, 8);
        v += __shfl_xor_sync(0xffffffffu, v, 4);
        v += __shfl_xor_sync(0xffffffffu, v, 2);
        v += __shfl_xor_sync(0xffffffffu, v, 1);
        if (tid == 0) g_scratch[blockIdx.x] = v;
    }

    // Quantized write — SCALAR stores (out+1 breaks 16B alignment)
    {
        float* qbase = out + OUT_Q + (size_t)b * CDIM * HW + hw0;
        const int lane = tid & 31;
        #pragma unroll
        for (int p = 0; p < 8; p++) {
            int c = (tid >> 5) + p * 8;
            #pragma unroll
            for (int q = 0; q < 4; q++) {
                int j = lane + q * 32;
                qbase[(size_t)c * HW + j] = qs[c * TM + j];
            }
        }
    }

    // ---- fused final loss ----
    __shared__ int s_last;
    __threadfence();
    if (tid == 0) {
        int old = atomicAdd(&g_count, 1);
        s_last = (old == NBLOCKS - 1) ? 1 : 0;
    }
    __syncthreads();
    if (s_last) {
        float v = g_scratch[tid] + g_scratch[tid + 256];
        v += __shfl_xor_sync(0xffffffffu, v, 16);
        v += __shfl_xor_sync(0xffffffffu, v, 8);
        v += __shfl_xor_sync(0xffffffffu, v, 4);
        v += __shfl_xor_sync(0xffffffffu, v, 2);
        v += __shfl_xor_sync(0xffffffffu, v, 1);
        if ((tid & 31) == 0) xn_s[tid >> 5] = v;
        __syncthreads();
        if (tid == 0) {
            float s = 0.f;
            #pragma unroll
            for (int w = 0; w < 8; w++) s += xn_s[w];
            out[0] = 0.25f * s / (float)ELEMS;
            g_count = 0;
        }
    }
}

extern "C" void kernel_launch(void* const* d_in, const int* in_sizes, int n_in,
                              void* d_out, int out_size) {
    const float* x   = (const float*)d_in[0];   // [16,64,64,64] NCHW
    const float* emb = (const float*)d_in[1];   // [1024,64]
    float* out = (float*)d_out;

    cudaFuncSetAttribute(vq_main, cudaFuncAttributeMaxDynamicSharedMemorySize,
                         SMEM_TOTAL);
    vq_prep<<<KTOT / 16, 256>>>(emb);
    vq_main<<<NBLOCKS, 256, SMEM_TOTAL>>>(x, emb, out);
}